// round 10
// baseline (speedup 1.0000x reference)
#include <cuda_runtime.h>

typedef unsigned long long ull;

#define NB 512
#define NS 1024
#define NL 64
#define NC 66
#define LN2 0.6931471805599453f

static __device__ __forceinline__ ull fma2_(ull a, ull b, ull c) {
    ull d; asm("fma.rn.f32x2 %0, %1, %2, %3;" : "=l"(d) : "l"(a), "l"(b), "l"(c)); return d;
}
static __device__ __forceinline__ ull add2_(ull a, ull b) {
    ull d; asm("add.rn.f32x2 %0, %1, %2;" : "=l"(d) : "l"(a), "l"(b)); return d;
}
static __device__ __forceinline__ ull pack2_(float lo, float hi) {
    ull d; asm("mov.b64 %0, {%1, %2};" : "=l"(d) : "f"(lo), "f"(hi)); return d;
}
static __device__ __forceinline__ float2 unpack2_(ull v) {
    float lo, hi; asm("mov.b64 {%0, %1}, %2;" : "=f"(lo), "=f"(hi) : "l"(v)); return make_float2(lo, hi);
}

__global__ void zero_out_kernel(float* out) { out[0] = 0.0f; }

// 128 threads = 2 chains; chain c = warps {2c, 2c+1} -> SMSPs {0,1} / {2,3}.
// Each thread owns ONE state: 32 FFMA2 per step (half of the single-warp design).
__global__ void __launch_bounds__(128, 1)
crf_fwd_kernel(const float* __restrict__ pred,
               const int*   __restrict__ ref,
               const int*   __restrict__ seq_len,
               const float* __restrict__ trans,
               float*       __restrict__ out)
{
    __shared__ __align__(16) float qbuf[2][2][64];
    __shared__ float red[2][2][2];
    __shared__ int Ls[2];

    const int tid = threadIdx.x;
    const int c   = tid >> 6;            // chain in CTA: 0..1
    const int j   = tid & 63;            // my state 0..63
    const int l   = tid & 31;            // lane
    const int hw  = (tid >> 5) & 1;      // which warp of the chain
    const int b   = blockIdx.x + (c ? 256 : 0);   // batch
    const int L   = seq_len[b];

    if (j == 0) Ls[c] = L;

    // E column for my state j: 32 f32x2 regs
    ull e2[32];
#pragma unroll
    for (int k = 0; k < 32; ++k)
        e2[k] = pack2_(__expf(trans[(2 * k) * NC + j]), __expf(trans[(2 * k + 1) * NC + j]));
    const float Te = __expf(trans[j * NC + 65]);

    const float* pb = pred + (size_t)b * NS * NL;
    const int last = L - 1;

    // init: q1 = exp(pred[0] + T[start])
    float q = __expf(pb[j] + trans[64 * NC + j]);
    qbuf[c][0][j] = q;

    float vthr = q * Te;    // terminal capture (covers L == 1)
    int ecap = 0, esum = 0;

    // pred pipeline (depth 3): at top of step t, w = exp(row[t-1] - 4)
    float r1 = pb[(size_t)min(1, last) * NL + j];
    float r2 = pb[(size_t)min(2, last) * NL + j];
    float w = __expf(r1 - 4.0f);
    r1 = r2;
    r2 = pb[(size_t)min(3, last) * NL + j];

    __syncthreads();
    const int Lmax = max(Ls[0], Ls[1]);

    for (int t = 2; t <= Lmax; ++t) {
        const float* rp = qbuf[c][t & 1];          // q_{t-1}
        float*       wp = qbuf[c][(t & 1) ^ 1];
        const ulonglong2* rp2 = (const ulonglong2*)rp;

        // d_j = sum_i q_{t-1}[i] * E[i][j] : 8 LDS.128 + 32 FFMA2 (4 accums)
        ull a0 = 0, a1 = 0, a2 = 0, a3 = 0;
#pragma unroll
        for (int k = 0; k < 8; ++k) {
            ulonglong2 v0 = rp2[2 * k];
            ulonglong2 v1 = rp2[2 * k + 1];
            a0 = fma2_(v0.x, e2[4 * k + 0], a0);
            a1 = fma2_(v0.y, e2[4 * k + 1], a1);
            a2 = fma2_(v1.x, e2[4 * k + 2], a2);
            a3 = fma2_(v1.y, e2[4 * k + 3], a3);
        }
        float2 f = unpack2_(add2_(add2_(a0, a1), add2_(a2, a3)));
        float d = (f.x + f.y) * w;

        // renorm every 8 steps (exact power of 2, uniform across the chain)
        if ((t & 7) == 0) {
            float m = rp[0];
            int e = ((__float_as_int(m) >> 23) & 0xFF) - 127;
            e = max(-100, min(100, e));
            d *= __int_as_float((unsigned)(127 - e) << 23);
            esum += e;
        }

        // branchless terminal capture at this chain's own length
        bool cap = (t == L);
        vthr = cap ? d * Te : vthr;
        ecap = cap ? esum   : ecap;

        wp[j] = d;

        // off-path: pipeline rotate
        w = __expf(r1 - 4.0f);
        r1 = r2;
        r2 = pb[(size_t)min(t + 2, last) * NL + j];

        __syncthreads();    // nw = 4, floor 7
    }

    // ---- real path score: chain's 64 threads stride time ----
    float rsum = 0.0f;
    const int* rb = ref + (size_t)b * NS;
    for (int s = j; s < L; s += 64) {
        int r = rb[s];
        int p = (s == 0) ? 64 : rb[s - 1];
        rsum += pb[(size_t)s * NL + r] + trans[p * NC + r];
    }
    if (j == 0) rsum += trans[rb[L - 1] * NC + 65];

    // ---- reduce per warp, then combine the chain's two warps ----
#pragma unroll
    for (int o = 16; o; o >>= 1) {
        vthr += __shfl_xor_sync(0xFFFFFFFFu, vthr, o);
        rsum += __shfl_xor_sync(0xFFFFFFFFu, rsum, o);
    }
    if (l == 0) {
        red[c][hw][0] = vthr;
        red[c][hw][1] = rsum;
    }
    __syncthreads();
    if (j == 0) {
        float s  = red[c][0][0] + red[c][1][0];
        float rs = red[c][0][1] + red[c][1][1];
        float contrib = 4.0f * (float)(L - 1) + LN2 * (float)ecap + __logf(s) - rs;
        atomicAdd(out, contrib);
    }
}

extern "C" void kernel_launch(void* const* d_in, const int* in_sizes, int n_in,
                              void* d_out, int out_size)
{
    const float* pred  = (const float*)d_in[0];
    const int*   refp  = (const int*)d_in[1];
    const int*   seq   = (const int*)d_in[2];
    const float* trans = (const float*)d_in[3];
    float* outp = (float*)d_out;

    zero_out_kernel<<<1, 1>>>(outp);
    crf_fwd_kernel<<<256, 128>>>(pred, refp, seq, trans, outp);
}